// round 16
// baseline (speedup 1.0000x reference)
#include <cuda_runtime.h>
#include <cuda_bf16.h>
#include <math.h>

#define NRES 768
#define HN   12
#define CH   16
#define CZ   128
#define PQN  4
#define PVN  8
#define CS   384

// ---------------- scratch (device globals; no allocation) ----------------
__device__ float g_q   [NRES * HN * CH];
__device__ float g_kv  [NRES * HN * 2 * CH];
__device__ float g_qp  [NRES * HN * PQN * 3];
__device__ float g_kvp [NRES * HN * 12 * 3];
__device__ float g_qpts[NRES * HN * PQN * 3];
__device__ float g_kpts[NRES * HN * PQN * 3];
__device__ float g_vpts[NRES * HN * PVN * 3];
__device__ float g_a   [HN * NRES * NRES];        // E logits, then softmaxed a
__device__ float g_b   [HN * NRES * NRES];        // bmat term
__device__ float g_obuf[NRES * HN * 40];
__device__ float g_opp [2 * NRES * HN * CZ];      // o_pair partials (2 m-halves)
__device__ float g_ocat[NRES * 2112];
__device__ float g_part[3 * NRES * CS];           // split-K out-gemm partials

// ---------------- cp.async + f32x2 helpers -----------------------------------
typedef unsigned long long u64;

__device__ __forceinline__ unsigned smem_u32(const void* p) {
    return (unsigned)__cvta_generic_to_shared(p);
}
__device__ __forceinline__ void cp_async16(unsigned dst, const void* src) {
    asm volatile("cp.async.cg.shared.global [%0], [%1], 16;" :: "r"(dst), "l"(src));
}
#define CP_COMMIT() asm volatile("cp.async.commit_group;" ::: "memory")
#define CP_WAIT(n)  asm volatile("cp.async.wait_group %0;" :: "n"(n) : "memory")

// packed fp32x2 FMA (Blackwell): d = a*b + d elementwise on 2 packed floats
__device__ __forceinline__ void fma2(u64& d, u64 a, u64 b) {
    asm("fma.rn.f32x2 %0, %1, %2, %3;" : "=l"(d) : "l"(a), "l"(b), "l"(d));
}
__device__ __forceinline__ u64 dup2(float v) {
    u64 d; asm("mov.b64 %0, {%1, %1};" : "=l"(d) : "f"(v)); return d;
}
__device__ __forceinline__ float2 unpack2(u64 d) {
    float2 r; asm("mov.b64 {%0, %1}, %2;" : "=f"(r.x), "=f"(r.y) : "l"(d)); return r;
}

// ---------------- GEMM body: C = A*W^T (+bias), f32x2 compute ----------------
__device__ __forceinline__ void gemm_body(const float* __restrict__ A,
                                          const float* __restrict__ W,
                                          const float* __restrict__ bias,
                                          float* __restrict__ C,
                                          int Nc, int ldA, int kbeg, int kend,
                                          int bm, int bn,
                                          float (*As)[68], float (*Bs)[68]) {
    const int tid = threadIdx.x;
    const int ty = tid >> 4, tx = tid & 15;
    u64 acc2[2][4];       // i-pairs (i0,i1),(i2,i3) x 4 j
#pragma unroll
    for (int p = 0; p < 2; p++)
#pragma unroll
        for (int j = 0; j < 4; j++) acc2[p][j] = 0ull;

    for (int k0 = kbeg; k0 < kend; k0 += 32) {
#pragma unroll
        for (int i = 0; i < 8; i++) {
            int idx = tid + i * 256;
            int r = idx >> 5, c = idx & 31;
            As[c][r] = A[(size_t)(bm + r) * ldA + k0 + c];
            int j = bn + r;
            Bs[c][r] = (j < Nc) ? W[(size_t)j * ldA + k0 + c] : 0.f;
        }
        __syncthreads();
#pragma unroll
        for (int kk = 0; kk < 32; kk++) {
            ulonglong2 ra = *(const ulonglong2*)&As[kk][ty * 4];
            float4 rb4 = *(const float4*)&Bs[kk][tx * 4];
            u64 rb[4] = {dup2(rb4.x), dup2(rb4.y), dup2(rb4.z), dup2(rb4.w)};
#pragma unroll
            for (int j = 0; j < 4; j++) {
                fma2(acc2[0][j], ra.x, rb[j]);
                fma2(acc2[1][j], ra.y, rb[j]);
            }
        }
        __syncthreads();
    }
#pragma unroll
    for (int p = 0; p < 2; p++) {
#pragma unroll
        for (int j = 0; j < 4; j++) {
            float2 u = unpack2(acc2[p][j]);
            int jj = bn + tx * 4 + j;
            if (jj < Nc) {
                float bv = bias ? bias[jj] : 0.f;
                int m0 = bm + ty * 4 + p * 2;
                C[(size_t)m0 * Nc + jj] = u.x + bv;
                C[(size_t)(m0 + 1) * Nc + jj] = u.y + bv;
            }
        }
    }
}

// ---------------- all 4 projections in one launch ---------------------------
__global__ void gemm_proj(const float* __restrict__ s,
                          const float* __restrict__ w_q,  const float* __restrict__ b_q,  float* pq,
                          const float* __restrict__ w_kv, const float* __restrict__ b_kv, float* pkv,
                          const float* __restrict__ w_qp, const float* __restrict__ b_qp, float* pqp,
                          const float* __restrict__ w_kvp,const float* __restrict__ b_kvp,float* pkvp) {
    __shared__ __align__(16) float As[32][68];
    __shared__ __align__(16) float Bs[32][68];
    const int x = blockIdx.x;
    const float *W, *bias; float* C; int Nc, bn;
    if (x < 3)       { W = w_q;   bias = b_q;   C = pq;   Nc = 192; bn = x; }
    else if (x < 9)  { W = w_kv;  bias = b_kv;  C = pkv;  Nc = 384; bn = x - 3; }
    else if (x < 12) { W = w_qp;  bias = b_qp;  C = pqp;  Nc = 144; bn = x - 9; }
    else             { W = w_kvp; bias = b_kvp; C = pkvp; Nc = 432; bn = x - 12; }
    gemm_body(s, W, bias, C, Nc, CS, 0, CS, blockIdx.y * 64, bn * 64, As, Bs);
}

// ---------------- split-K output gemm + combine ------------------------------
__global__ void gemm_out(const float* __restrict__ A, const float* __restrict__ W,
                         float* __restrict__ P) {
    __shared__ __align__(16) float As[32][68];
    __shared__ __align__(16) float Bs[32][68];
    const int seg = blockIdx.z;
    gemm_body(A, W, (const float*)0, P + (size_t)seg * NRES * CS,
              CS, 2112, seg * 704, (seg + 1) * 704,
              blockIdx.y * 64, blockIdx.x * 64, As, Bs);
}
__global__ void k_outadd(const float* __restrict__ b_out, float* __restrict__ out) {
    const int n = blockIdx.x, t = threadIdx.x;   // 384 threads
    size_t i = (size_t)n * CS + t;
    out[i] = g_part[i] + g_part[(size_t)NRES * CS + i] +
             g_part[2 * (size_t)NRES * CS + i] + b_out[t];
}

// ---------------- point transform -------------------------------------------
__global__ void k_points(const float* __restrict__ rot, const float* __restrict__ trans) {
    int n = blockIdx.x;
    int t = threadIdx.x;   // 192 threads
    const float* r = rot + n * 9;
    float t0 = trans[n * 3 + 0], t1 = trans[n * 3 + 1], t2 = trans[n * 3 + 2];
    if (t < 48) {
        float x = g_qp[n * 144 + t];
        float y = g_qp[n * 144 + 48 + t];
        float z = g_qp[n * 144 + 96 + t];
        float o0 = r[0] * x + r[1] * y + r[2] * z + t0;
        float o1 = r[3] * x + r[4] * y + r[5] * z + t1;
        float o2 = r[6] * x + r[7] * y + r[8] * z + t2;
        g_qpts[n * 144 + t * 3 + 0] = o0;
        g_qpts[n * 144 + t * 3 + 1] = o1;
        g_qpts[n * 144 + t * 3 + 2] = o2;
    } else {
        int p = t - 48;
        float x = g_kvp[n * 432 + p];
        float y = g_kvp[n * 432 + 144 + p];
        float z = g_kvp[n * 432 + 288 + p];
        float o0 = r[0] * x + r[1] * y + r[2] * z + t0;
        float o1 = r[3] * x + r[4] * y + r[5] * z + t1;
        float o2 = r[6] * x + r[7] * y + r[8] * z + t2;
        int h = p / 12, pp = p % 12;
        if (pp < 4) {
            int base = n * 144 + (h * 4 + pp) * 3;
            g_kpts[base + 0] = o0; g_kpts[base + 1] = o1; g_kpts[base + 2] = o2;
        } else {
            int base = n * 288 + (h * 8 + (pp - 4)) * 3;
            g_vpts[base + 0] = o0; g_vpts[base + 1] = o1; g_vpts[base + 2] = o2;
        }
    }
}

// ---------------- phase1 bodies ----------------------------------------------
// bmat: g_b = s3*(z.w_b + b_b), cp.async double-buffered, f32x2 compute.
#define B4_PAD  36
#define B4_BUF  (128 * B4_PAD)                 // 4608 words per buffer
#define B4_SMEM ((2 * B4_BUF + HN * CZ + 16) * 4)   // ~43.1 KB
__device__ void bmat_body(float* sh, const float* __restrict__ z,
                          const float* __restrict__ w_b, const float* __restrict__ b_b,
                          int m0, int n) {
    float* zbuf = sh;
    float* wsh  = sh + 2 * B4_BUF;
    float* bsh  = wsh + HN * CZ;
    float* psum = sh;                          // overlay on zbuf after compute (3072 <= 9216)
    const int tid = threadIdx.x;

    const float* zsrc = z + ((size_t)n * NRES + m0) * CZ;
    {
        unsigned dstb = smem_u32(zbuf);
#pragma unroll
        for (int j = 0; j < 4; j++) {
            int i = tid + j * 256;
            int m = i >> 3, c4 = i & 7;
            cp_async16(dstb + (m * B4_PAD + c4 * 4) * 4, zsrc + m * CZ + c4 * 4);
        }
        CP_COMMIT();
    }
    for (int idx = tid; idx < HN * CZ; idx += 256) wsh[idx] = w_b[idx];
    if (tid < HN) bsh[tid] = b_b[tid];

    const int mg = tid & 63;         // rows mg and mg+64
    const int ch = (tid >> 6) & 1;   // c half (16c of the 32c chunk)
    const int hg = tid >> 7;         // head group (6 heads)
    u64 acc0[6], acc1[6];
#pragma unroll
    for (int j = 0; j < 6; j++) { acc0[j] = 0ull; acc1[j] = 0ull; }

    for (int cc = 0; cc < 4; cc++) {
        if (cc < 3) {
            unsigned dstb = smem_u32(zbuf + ((cc + 1) & 1) * B4_BUF);
            const float* src = zsrc + (cc + 1) * 32;
#pragma unroll
            for (int j = 0; j < 4; j++) {
                int i = tid + j * 256;
                int m = i >> 3, c4 = i & 7;
                cp_async16(dstb + (m * B4_PAD + c4 * 4) * 4, src + m * CZ + c4 * 4);
            }
            CP_COMMIT();
            CP_WAIT(1);
        } else {
            CP_WAIT(0);
        }
        __syncthreads();

        const float* zr0 = zbuf + (cc & 1) * B4_BUF + mg * B4_PAD + ch * 16;
        const float* zr1 = zr0 + 64 * B4_PAD;
        const float* wr  = wsh + hg * 6 * CZ + cc * 32 + ch * 16;
#pragma unroll
        for (int i4 = 0; i4 < 4; i4++) {
            ulonglong2 za = *(const ulonglong2*)&zr0[i4 * 4];
            ulonglong2 zb = *(const ulonglong2*)&zr1[i4 * 4];
#pragma unroll
            for (int j = 0; j < 6; j++) {
                ulonglong2 w = *(const ulonglong2*)&wr[j * CZ + i4 * 4];
                fma2(acc0[j], za.x, w.x);
                fma2(acc0[j], za.y, w.y);
                fma2(acc1[j], zb.x, w.x);
                fma2(acc1[j], zb.y, w.y);
            }
        }
        __syncthreads();
    }

    // psum overlay on zbuf: psum[ch][row(128)][12]
#pragma unroll
    for (int j = 0; j < 6; j++) {
        float2 u0 = unpack2(acc0[j]);
        float2 u1 = unpack2(acc1[j]);
        psum[ch * 1536 + mg * 12 + hg * 6 + j] = u0.x + u0.y;
        psum[ch * 1536 + (mg + 64) * 12 + hg * 6 + j] = u1.x + u1.y;
    }
    __syncthreads();

    const float s3 = 0.5773502691896258f;
    for (int out = tid; out < 128 * HN; out += 256) {
        int h = out >> 7, m = out & 127;       // m fastest -> coalesced
        float dot = psum[m * 12 + h] + psum[1536 + m * 12 + h];
        g_b[((size_t)h * NRES + n) * NRES + m0 + m] = s3 * (dot + bsh[h]);
    }
}

// qkpt: E = s1*qk - |wpt|*ptdist + mask -> g_a
__device__ void qkpt_body(float* sh, const float* __restrict__ mask,
                          const float* __restrict__ head_weights,
                          int h, int n0, int m0) {
    float (*Qs)[68] = (float(*)[68])sh;
    float (*Ks)[68] = (float(*)[68])(sh + 28 * 68);
    const int tid = threadIdx.x;
    const float s1 = 0.14433756729740643f;
    const float hw = log1pf(expf(head_weights[h]));
    const float wpt_abs = 0.5f * hw * 0.13608276348795434f;
    const float sp = sqrtf(wpt_abs);

    for (int idx = tid; idx < 64 * 32; idx += 256) {
        int c = idx & 31, r = idx >> 5;
        if (c < 16) {
            Qs[c][r] = s1 * g_q[(n0 + r) * 192 + h * 16 + c];
            Ks[c][r] = g_kv[(size_t)(m0 + r) * 384 + h * 32 + c];
        } else if (c < 28) {
            Qs[c][r] = sp * g_qpts[(n0 + r) * 144 + h * 12 + (c - 16)];
            Ks[c][r] = sp * g_kpts[(m0 + r) * 144 + h * 12 + (c - 16)];
        }
    }
    __syncthreads();
    const int ty = tid >> 4, tx = tid & 15;
    float acc[4][4];
#pragma unroll
    for (int i = 0; i < 4; i++)
#pragma unroll
        for (int j = 0; j < 4; j++) acc[i][j] = 0.f;

#pragma unroll
    for (int c = 0; c < 16; c++) {
        float ra[4], rb[4];
#pragma unroll
        for (int i = 0; i < 4; i++) ra[i] = Qs[c][ty * 4 + i];
#pragma unroll
        for (int j = 0; j < 4; j++) rb[j] = Ks[c][tx * 4 + j];
#pragma unroll
        for (int i = 0; i < 4; i++)
#pragma unroll
            for (int j = 0; j < 4; j++) acc[i][j] += ra[i] * rb[j];
    }
#pragma unroll
    for (int c = 16; c < 28; c++) {
        float ra[4], rb[4];
#pragma unroll
        for (int i = 0; i < 4; i++) ra[i] = Qs[c][ty * 4 + i];
#pragma unroll
        for (int j = 0; j < 4; j++) rb[j] = Ks[c][tx * 4 + j];
#pragma unroll
        for (int i = 0; i < 4; i++)
#pragma unroll
            for (int j = 0; j < 4; j++) {
                float d = ra[i] - rb[j];
                acc[i][j] = fmaf(-d, d, acc[i][j]);
            }
    }
#pragma unroll
    for (int i = 0; i < 4; i++) {
        int n = n0 + ty * 4 + i;
        float mn = mask[n];
#pragma unroll
        for (int j = 0; j < 4; j++) {
            int m = m0 + tx * 4 + j;
            g_a[((size_t)h * NRES + n) * NRES + m] =
                acc[i][j] + (mn * mask[m] - 1.f) * 100000.f;
        }
    }
}

// phase1: interleave 8 bmat : 3 qkpt per group of 11 blocks (4608 + 1728)
__global__ __launch_bounds__(256, 5) void k_phase1(
        const float* __restrict__ z, const float* __restrict__ w_b,
        const float* __restrict__ b_b, const float* __restrict__ mask,
        const float* __restrict__ head_weights) {
    extern __shared__ float sh[];
    const int q = blockIdx.x / 11, r = blockIdx.x % 11;
    if (r < 8) {
        int b = q * 8 + r;
        bmat_body(sh, z, w_b, b_b, (b % 6) * 128, b / 6);
    } else {
        int t = q * 3 + (r - 8);              // 0..1727
        int h = t % 12; t /= 12;
        qkpt_body(sh, mask, head_weights, h, (t % 12) * 64, (t / 12) * 64);
    }
}

// ---------------- softmax over m: a = softmax(E + B), float4 + shuffle -------
__global__ void k_softmax() {
    __shared__ float red[8];
    const size_t row = blockIdx.x;
    float4* a4 = (float4*)(g_a + row * NRES);
    const float4* b4 = (const float4*)(g_b + row * NRES);
    const int t = threadIdx.x;             // 192 threads, 1 float4 each
    const int lane = t & 31, wid = t >> 5;
    float4 v = a4[t];
    float4 bb = b4[t];
    v.x += bb.x; v.y += bb.y; v.z += bb.z; v.w += bb.w;
    float mx = fmaxf(fmaxf(v.x, v.y), fmaxf(v.z, v.w));
#pragma unroll
    for (int o = 16; o > 0; o >>= 1) mx = fmaxf(mx, __shfl_xor_sync(0xffffffffu, mx, o));
    if (lane == 0) red[wid] = mx;
    __syncthreads();
    mx = fmaxf(fmaxf(red[0], red[1]),
               fmaxf(fmaxf(red[2], red[3]), fmaxf(red[4], red[5])));
    __syncthreads();                        // red reads done before reuse
    v.x = __expf(v.x - mx); v.y = __expf(v.y - mx);
    v.z = __expf(v.z - mx); v.w = __expf(v.w - mx);
    float sum = v.x + v.y + v.z + v.w;
#pragma unroll
    for (int o = 16; o > 0; o >>= 1) sum += __shfl_xor_sync(0xffffffffu, sum, o);
    if (lane == 0) red[wid] = sum;
    __syncthreads();
    float inv = 1.f / (red[0] + red[1] + red[2] + red[3] + red[4] + red[5]);
    v.x *= inv; v.y *= inv; v.z *= inv; v.w *= inv;
    a4[t] = v;
}

// ---------------- phase2 bodies ----------------------------------------------
// opair: double-buffered 16m chunks; ash [m][16]; f32x2 over c-pairs;
// psum overlays zbuf + head of ash (both dead after compute loop).
#define O6_CH   16
#define O6_NCH  24
#define O6_BUF  (O6_CH * CZ)                   // 2048 words
#define O6_ASZ  (384 * 16)                     // 6144 padded transposed
#define P2_SMEM ((2 * O6_BUF + O6_ASZ) * 4)    // 40 KB
__device__ void opair_body(float* sh, const float* __restrict__ z, int n, int half) {
    float* zbuf = sh;                          // 2 x 2048
    float* ash  = sh + 2 * O6_BUF;             // [384][16]
    float* psum = sh;                          // overlay: 6144 w over zbuf+ash head
    const int tid  = threadIdx.x;
    const int mbase = half * 384;
    const float* zsrc = z + ((size_t)n * NRES + mbase) * CZ;

    // prefetch chunk 0
    {
        unsigned dstb = smem_u32(zbuf);
#pragma unroll
        for (int j = 0; j < 2; j++) {
            int i = tid + j * 256;             // 512 float4
            cp_async16(dstb + i * 16, zsrc + i * 4);
        }
        CP_COMMIT();
    }

    // transposed a staging: ash[m][ (h/6)*8 + h%6 ]
    for (int idx = tid; idx < HN * 384; idx += 256) {
        int h = idx / 384, m = idx - h * 384;
        int col = (h / 6) * 8 + (h % 6);
        ash[m * 16 + col] = g_a[((size_t)h * NRES + n) * NRES + mbase + m];
    }

    const int mw = tid >> 6;         // 0..3  m-group (4 m each per chunk)
    const int hg = (tid >> 5) & 1;   // head group (6 heads)
    const int cg = tid & 31;         // 4 c's per lane
    u64 acc2[6][2];                  // [head][c-pair]
#pragma unroll
    for (int j = 0; j < 6; j++) { acc2[j][0] = 0ull; acc2[j][1] = 0ull; }

    for (int k = 0; k < O6_NCH; k++) {
        if (k + 1 < O6_NCH) {
            unsigned dstb = smem_u32(zbuf + ((k + 1) & 1) * O6_BUF);
            const float* src = zsrc + (size_t)(k + 1) * O6_CH * CZ;
#pragma unroll
            for (int j = 0; j < 2; j++) {
                int i = tid + j * 256;
                cp_async16(dstb + i * 16, src + i * 4);
            }
            CP_COMMIT();
            CP_WAIT(1);
        } else {
            CP_WAIT(0);
        }
        __syncthreads();

        const float* zb = zbuf + (k & 1) * O6_BUF;
        const int mg0 = k * O6_CH + mw * 4;
#pragma unroll
        for (int mm = 0; mm < 4; mm++) {
            int ml = mw * 4 + mm;
            ulonglong2 zv = *(const ulonglong2*)&zb[ml * CZ + cg * 4];
            const float* ar = &ash[(mg0 + mm) * 16 + hg * 8];
            float4 a0 = *(const float4*)&ar[0];
            float2 a1 = *(const float2*)&ar[4];
            u64 ad[6] = {dup2(a0.x), dup2(a0.y), dup2(a0.z),
                         dup2(a0.w), dup2(a1.x), dup2(a1.y)};
#pragma unroll
            for (int j = 0; j < 6; j++) {
                fma2(acc2[j][0], ad[j], zv.x);
                fma2(acc2[j][1], ad[j], zv.y);
            }
        }
        __syncthreads();
    }

    // psum overlay: psum[mw][12][128] (6144 words; ash dead now)
#pragma unroll
    for (int j = 0; j < 6; j++) {
        float2 u0 = unpack2(acc2[j][0]);
        float2 u1 = unpack2(acc2[j][1]);
        *(float4*)&psum[mw * 1536 + (hg * 6 + j) * CZ + cg * 4] =
            make_float4(u0.x, u0.y, u1.x, u1.y);
    }
    __syncthreads();
    for (int out = tid; out < HN * CZ; out += 256) {
        const float* pb = psum + out;
        float s = pb[0] + pb[1536] + pb[3072] + pb[4608];
        g_opp[((size_t)half * NRES + n) * (HN * CZ) + out] = s;
    }
}

// av: o = a@v, o_pt = a@v_pts (global frame)
__device__ void av_body(float* sh, int h, int n0) {
    float* ash = sh;                 // 64*65
    float* vsh = sh + 64 * 65;       // 64*48
    const int tid = threadIdx.x;
    const int nq = tid & 15, cg = tid >> 4;
    float acc[4][3];
#pragma unroll
    for (int i = 0; i < 4; i++)
#pragma unroll
        for (int j = 0; j < 3; j++) acc[i][j] = 0.f;

    for (int mt = 0; mt < 12; mt++) {
        const int m0 = mt * 64;
        __syncthreads();
        for (int idx = tid; idx < 4096; idx += 256) {
            int nn = idx >> 6, mm = idx & 63;
            ash[nn * 65 + mm] = g_a[((size_t)h * NRES + n0 + nn) * NRES + m0 + mm];
        }
        for (int idx = tid; idx < 64 * 48; idx += 256) {
            int mm = idx / 48, c = idx % 48;
            float v = 0.f;
            if (c < 16)      v = g_kv[(size_t)(m0 + mm) * 384 + h * 32 + 16 + c];
            else if (c < 40) v = g_vpts[(m0 + mm) * 288 + h * 24 + (c - 16)];
            vsh[mm * 48 + c] = v;
        }
        __syncthreads();
#pragma unroll 4
        for (int mm = 0; mm < 64; mm++) {
            float ra[4], rv[3];
#pragma unroll
            for (int i = 0; i < 4; i++) ra[i] = ash[(nq + 16 * i) * 65 + mm];
#pragma unroll
            for (int j = 0; j < 3; j++) rv[j] = vsh[mm * 48 + cg + 16 * j];
#pragma unroll
            for (int i = 0; i < 4; i++)
#pragma unroll
                for (int j = 0; j < 3; j++) acc[i][j] += ra[i] * rv[j];
        }
    }
#pragma unroll
    for (int i = 0; i < 4; i++) {
        int n = n0 + nq + 16 * i;
#pragma unroll
        for (int j = 0; j < 3; j++) {
            int c = cg + 16 * j;
            if (c < 40) g_obuf[((size_t)n * 12 + h) * 40 + c] = acc[i][j];
        }
    }
}

// phase2: interleave 32 opair : 3 av per group of 35 blocks (1536 + 144)
__global__ __launch_bounds__(256, 5) void k_phase2(const float* __restrict__ z) {
    extern __shared__ float sh[];
    const int q = blockIdx.x / 35, r = blockIdx.x % 35;
    if (r < 32) {
        int b = q * 32 + r;
        opair_body(sh, z, b >> 1, b & 1);
    } else {
        int t = q * 3 + (r - 32);             // 0..143
        av_body(sh, t % 12, (t / 12) * 64);
    }
}

// ---------------- finalize: o_pt local frame, norms, concat, opp sum --------
__global__ void k_finish(const float* __restrict__ rot, const float* __restrict__ trans) {
    const int n = blockIdx.x;
    const int t = threadIdx.x;   // 192
    if (t < 96) {
        int h = t >> 3, p = t & 7;
        const float* ob = &g_obuf[((size_t)n * 12 + h) * 40 + 16 + p * 3];
        float gx = ob[0] - trans[n * 3 + 0];
        float gy = ob[1] - trans[n * 3 + 1];
        float gz = ob[2] - trans[n * 3 + 2];
        const float* r = rot + n * 9;
        float lx = r[0] * gx + r[3] * gy + r[6] * gz;
        float ly = r[1] * gx + r[4] * gy + r[7] * gz;
        float lz = r[2] * gx + r[5] * gy + r[8] * gz;
        size_t base = (size_t)n * 2112;
        g_ocat[base + 192 + t] = lx;
        g_ocat[base + 288 + t] = ly;
        g_ocat[base + 384 + t] = lz;
        g_ocat[base + 480 + t] = sqrtf(lx * lx + ly * ly + lz * lz + 1e-8f);
    }
    g_ocat[(size_t)n * 2112 + t] = g_obuf[((size_t)n * 12 + (t >> 4)) * 40 + (t & 15)];
    for (int i = t; i < HN * CZ; i += 192) {
        g_ocat[(size_t)n * 2112 + 576 + i] =
            g_opp[(size_t)n * (HN * CZ) + i] +
            g_opp[((size_t)NRES + n) * (HN * CZ) + i];
    }
}

// ---------------- launcher ---------------------------------------------------
extern "C" void kernel_launch(void* const* d_in, const int* in_sizes, int n_in,
                              void* d_out, int out_size) {
    const float* s      = (const float*)d_in[0];
    const float* z      = (const float*)d_in[1];
    const float* rot    = (const float*)d_in[2];
    const float* trans  = (const float*)d_in[3];
    const float* mask   = (const float*)d_in[4];
    const float* w_q    = (const float*)d_in[5];
    const float* b_q    = (const float*)d_in[6];
    const float* w_kv   = (const float*)d_in[7];
    const float* b_kv   = (const float*)d_in[8];
    const float* w_qp   = (const float*)d_in[9];
    const float* b_qp   = (const float*)d_in[10];
    const float* w_kvp  = (const float*)d_in[11];
    const float* b_kvp  = (const float*)d_in[12];
    const float* w_b    = (const float*)d_in[13];
    const float* b_b    = (const float*)d_in[14];
    const float* hwts   = (const float*)d_in[15];
    const float* w_out  = (const float*)d_in[16];
    const float* b_out  = (const float*)d_in[17];
    float* out = (float*)d_out;

    float *pq, *pkv, *pqp, *pkvp, *pocat, *ppart;
    cudaGetSymbolAddress((void**)&pq,    g_q);
    cudaGetSymbolAddress((void**)&pkv,   g_kv);
    cudaGetSymbolAddress((void**)&pqp,   g_qp);
    cudaGetSymbolAddress((void**)&pkvp,  g_kvp);
    cudaGetSymbolAddress((void**)&pocat, g_ocat);
    cudaGetSymbolAddress((void**)&ppart, g_part);

    cudaFuncSetAttribute(k_phase1, cudaFuncAttributeMaxDynamicSharedMemorySize, B4_SMEM);
    cudaFuncSetAttribute(k_phase2, cudaFuncAttributeMaxDynamicSharedMemorySize, P2_SMEM);

    // projections (one launch)
    gemm_proj<<<dim3(19, 12), 256>>>(s, w_q, b_q, pq, w_kv, b_kv, pkv,
                                     w_qp, b_qp, pqp, w_kvp, b_kvp, pkvp);
    // point transform
    k_points<<<NRES, 192>>>(rot, trans);
    // phase1: bmat (z pass 1) + qkpt interleaved
    k_phase1<<<6336, 256, B4_SMEM>>>(z, w_b, b_b, mask, hwts);
    // softmax(E + B) -> g_a
    k_softmax<<<HN * NRES, 192>>>();
    // phase2: opair (z pass 2) + av interleaved
    k_phase2<<<1680, 256, P2_SMEM>>>(z);
    k_finish<<<NRES, 192>>>(rot, trans);
    // output projection: split-K x3 + combine
    gemm_out<<<dim3(6, 12, 3), 256>>>(pocat, w_out, ppart);
    k_outadd<<<NRES, CS>>>(b_out, out);
}

// round 17
// speedup vs baseline: 1.0731x; 1.0731x over previous
#include <cuda_runtime.h>
#include <cuda_bf16.h>
#include <math.h>

#define NRES 768
#define HN   12
#define CH   16
#define CZ   128
#define PQN  4
#define PVN  8
#define CS   384

// ---------------- scratch (device globals; no allocation) ----------------
__device__ float g_q   [NRES * HN * CH];
__device__ float g_kv  [NRES * HN * 2 * CH];
__device__ float g_qp  [NRES * HN * PQN * 3];
__device__ float g_kvp [NRES * HN * 12 * 3];
__device__ float g_qpts[NRES * HN * PQN * 3];
__device__ float g_kpts[NRES * HN * PQN * 3];
__device__ float g_vpts[NRES * HN * PVN * 3];
__device__ float g_a   [HN * NRES * NRES];        // E logits, then softmaxed a
__device__ float g_b   [HN * NRES * NRES];        // bmat term
__device__ float g_obuf[NRES * HN * 40];
__device__ float g_opp [2 * NRES * HN * CZ];      // o_pair partials (2 m-halves)
__device__ float g_ocat[NRES * 2112];
__device__ float g_part[3 * NRES * CS];           // split-K out-gemm partials

// ---------------- cp.async + f32x2 helpers -----------------------------------
typedef unsigned long long u64;

__device__ __forceinline__ unsigned smem_u32(const void* p) {
    return (unsigned)__cvta_generic_to_shared(p);
}
__device__ __forceinline__ void cp_async16(unsigned dst, const void* src) {
    asm volatile("cp.async.cg.shared.global [%0], [%1], 16;" :: "r"(dst), "l"(src));
}
#define CP_COMMIT() asm volatile("cp.async.commit_group;" ::: "memory")
#define CP_WAIT(n)  asm volatile("cp.async.wait_group %0;" :: "n"(n) : "memory")

// packed fp32x2 FMA (Blackwell): d = a*b + d elementwise on 2 packed floats
__device__ __forceinline__ void fma2(u64& d, u64 a, u64 b) {
    asm("fma.rn.f32x2 %0, %1, %2, %3;" : "=l"(d) : "l"(a), "l"(b), "l"(d));
}
__device__ __forceinline__ u64 dup2(float v) {
    u64 d; asm("mov.b64 %0, {%1, %1};" : "=l"(d) : "f"(v)); return d;
}
__device__ __forceinline__ float2 unpack2(u64 d) {
    float2 r; asm("mov.b64 {%0, %1}, %2;" : "=f"(r.x), "=f"(r.y) : "l"(d)); return r;
}

// ---------------- GEMM body: C = A*W^T (+bias), f32x2 compute ----------------
__device__ __forceinline__ void gemm_body(const float* __restrict__ A,
                                          const float* __restrict__ W,
                                          const float* __restrict__ bias,
                                          float* __restrict__ C,
                                          int Nc, int ldA, int kbeg, int kend,
                                          int bm, int bn,
                                          float (*As)[68], float (*Bs)[68]) {
    const int tid = threadIdx.x;
    const int ty = tid >> 4, tx = tid & 15;
    u64 acc2[2][4];       // i-pairs (i0,i1),(i2,i3) x 4 j
#pragma unroll
    for (int p = 0; p < 2; p++)
#pragma unroll
        for (int j = 0; j < 4; j++) acc2[p][j] = 0ull;

    for (int k0 = kbeg; k0 < kend; k0 += 32) {
#pragma unroll
        for (int i = 0; i < 8; i++) {
            int idx = tid + i * 256;
            int r = idx >> 5, c = idx & 31;
            As[c][r] = A[(size_t)(bm + r) * ldA + k0 + c];
            int j = bn + r;
            Bs[c][r] = (j < Nc) ? W[(size_t)j * ldA + k0 + c] : 0.f;
        }
        __syncthreads();
#pragma unroll
        for (int kk = 0; kk < 32; kk++) {
            ulonglong2 ra = *(const ulonglong2*)&As[kk][ty * 4];
            float4 rb4 = *(const float4*)&Bs[kk][tx * 4];
            u64 rb[4] = {dup2(rb4.x), dup2(rb4.y), dup2(rb4.z), dup2(rb4.w)};
#pragma unroll
            for (int j = 0; j < 4; j++) {
                fma2(acc2[0][j], ra.x, rb[j]);
                fma2(acc2[1][j], ra.y, rb[j]);
            }
        }
        __syncthreads();
    }
#pragma unroll
    for (int p = 0; p < 2; p++) {
#pragma unroll
        for (int j = 0; j < 4; j++) {
            float2 u = unpack2(acc2[p][j]);
            int jj = bn + tx * 4 + j;
            if (jj < Nc) {
                float bv = bias ? bias[jj] : 0.f;
                int m0 = bm + ty * 4 + p * 2;
                C[(size_t)m0 * Nc + jj] = u.x + bv;
                C[(size_t)(m0 + 1) * Nc + jj] = u.y + bv;
            }
        }
    }
}

// ---------------- all 4 projections in one launch ---------------------------
__global__ void gemm_proj(const float* __restrict__ s,
                          const float* __restrict__ w_q,  const float* __restrict__ b_q,  float* pq,
                          const float* __restrict__ w_kv, const float* __restrict__ b_kv, float* pkv,
                          const float* __restrict__ w_qp, const float* __restrict__ b_qp, float* pqp,
                          const float* __restrict__ w_kvp,const float* __restrict__ b_kvp,float* pkvp) {
    __shared__ __align__(16) float As[32][68];
    __shared__ __align__(16) float Bs[32][68];
    const int x = blockIdx.x;
    const float *W, *bias; float* C; int Nc, bn;
    if (x < 3)       { W = w_q;   bias = b_q;   C = pq;   Nc = 192; bn = x; }
    else if (x < 9)  { W = w_kv;  bias = b_kv;  C = pkv;  Nc = 384; bn = x - 3; }
    else if (x < 12) { W = w_qp;  bias = b_qp;  C = pqp;  Nc = 144; bn = x - 9; }
    else             { W = w_kvp; bias = b_kvp; C = pkvp; Nc = 432; bn = x - 12; }
    gemm_body(s, W, bias, C, Nc, CS, 0, CS, blockIdx.y * 64, bn * 64, As, Bs);
}

// ---------------- split-K output gemm + combine ------------------------------
__global__ void gemm_out(const float* __restrict__ A, const float* __restrict__ W,
                         float* __restrict__ P) {
    __shared__ __align__(16) float As[32][68];
    __shared__ __align__(16) float Bs[32][68];
    const int seg = blockIdx.z;
    gemm_body(A, W, (const float*)0, P + (size_t)seg * NRES * CS,
              CS, 2112, seg * 704, (seg + 1) * 704,
              blockIdx.y * 64, blockIdx.x * 64, As, Bs);
}
__global__ void k_outadd(const float* __restrict__ b_out, float* __restrict__ out) {
    const int n = blockIdx.x, t = threadIdx.x;   // 384 threads
    size_t i = (size_t)n * CS + t;
    out[i] = g_part[i] + g_part[(size_t)NRES * CS + i] +
             g_part[2 * (size_t)NRES * CS + i] + b_out[t];
}

// ---------------- point transform -------------------------------------------
__global__ void k_points(const float* __restrict__ rot, const float* __restrict__ trans) {
    int n = blockIdx.x;
    int t = threadIdx.x;   // 192 threads
    const float* r = rot + n * 9;
    float t0 = trans[n * 3 + 0], t1 = trans[n * 3 + 1], t2 = trans[n * 3 + 2];
    if (t < 48) {
        float x = g_qp[n * 144 + t];
        float y = g_qp[n * 144 + 48 + t];
        float z = g_qp[n * 144 + 96 + t];
        float o0 = r[0] * x + r[1] * y + r[2] * z + t0;
        float o1 = r[3] * x + r[4] * y + r[5] * z + t1;
        float o2 = r[6] * x + r[7] * y + r[8] * z + t2;
        g_qpts[n * 144 + t * 3 + 0] = o0;
        g_qpts[n * 144 + t * 3 + 1] = o1;
        g_qpts[n * 144 + t * 3 + 2] = o2;
    } else {
        int p = t - 48;
        float x = g_kvp[n * 432 + p];
        float y = g_kvp[n * 432 + 144 + p];
        float z = g_kvp[n * 432 + 288 + p];
        float o0 = r[0] * x + r[1] * y + r[2] * z + t0;
        float o1 = r[3] * x + r[4] * y + r[5] * z + t1;
        float o2 = r[6] * x + r[7] * y + r[8] * z + t2;
        int h = p / 12, pp = p % 12;
        if (pp < 4) {
            int base = n * 144 + (h * 4 + pp) * 3;
            g_kpts[base + 0] = o0; g_kpts[base + 1] = o1; g_kpts[base + 2] = o2;
        } else {
            int base = n * 288 + (h * 8 + (pp - 4)) * 3;
            g_vpts[base + 0] = o0; g_vpts[base + 1] = o1; g_vpts[base + 2] = o2;
        }
    }
}

// ---------------- phase1 bodies ----------------------------------------------
// bmat: g_b = s3*(z.w_b + b_b), cp.async double-buffered, f32x2 compute.
// Thread = 2 m-rows x 6 heads x 16c-half; acc packed over c-pairs.
#define B4_PAD  36
#define B4_BUF  (128 * B4_PAD)                 // 4608 words per buffer
#define B4_SMEM ((2 * B4_BUF + HN * CZ + 16) * 4)   // ~43.1 KB
__device__ void bmat_body(float* sh, const float* __restrict__ z,
                          const float* __restrict__ w_b, const float* __restrict__ b_b,
                          int m0, int n) {
    float* zbuf = sh;
    float* wsh  = sh + 2 * B4_BUF;
    float* bsh  = wsh + HN * CZ;
    float* psum = sh;                          // overlay on zbuf after compute (3072 <= 9216)
    const int tid = threadIdx.x;

    const float* zsrc = z + ((size_t)n * NRES + m0) * CZ;
    {
        unsigned dstb = smem_u32(zbuf);
#pragma unroll
        for (int j = 0; j < 4; j++) {
            int i = tid + j * 256;
            int m = i >> 3, c4 = i & 7;
            cp_async16(dstb + (m * B4_PAD + c4 * 4) * 4, zsrc + m * CZ + c4 * 4);
        }
        CP_COMMIT();
    }
    for (int idx = tid; idx < HN * CZ; idx += 256) wsh[idx] = w_b[idx];
    if (tid < HN) bsh[tid] = b_b[tid];

    const int mg = tid & 63;         // rows mg and mg+64
    const int ch = (tid >> 6) & 1;   // c half (16c of the 32c chunk)
    const int hg = tid >> 7;         // head group (6 heads)
    u64 acc0[6], acc1[6];
#pragma unroll
    for (int j = 0; j < 6; j++) { acc0[j] = 0ull; acc1[j] = 0ull; }

    for (int cc = 0; cc < 4; cc++) {
        if (cc < 3) {
            unsigned dstb = smem_u32(zbuf + ((cc + 1) & 1) * B4_BUF);
            const float* src = zsrc + (cc + 1) * 32;
#pragma unroll
            for (int j = 0; j < 4; j++) {
                int i = tid + j * 256;
                int m = i >> 3, c4 = i & 7;
                cp_async16(dstb + (m * B4_PAD + c4 * 4) * 4, src + m * CZ + c4 * 4);
            }
            CP_COMMIT();
            CP_WAIT(1);
        } else {
            CP_WAIT(0);
        }
        __syncthreads();

        const float* zr0 = zbuf + (cc & 1) * B4_BUF + mg * B4_PAD + ch * 16;
        const float* zr1 = zr0 + 64 * B4_PAD;
        const float* wr  = wsh + hg * 6 * CZ + cc * 32 + ch * 16;
#pragma unroll
        for (int i4 = 0; i4 < 4; i4++) {
            ulonglong2 za = *(const ulonglong2*)&zr0[i4 * 4];
            ulonglong2 zb = *(const ulonglong2*)&zr1[i4 * 4];
#pragma unroll
            for (int j = 0; j < 6; j++) {
                ulonglong2 w = *(const ulonglong2*)&wr[j * CZ + i4 * 4];
                fma2(acc0[j], za.x, w.x);
                fma2(acc0[j], za.y, w.y);
                fma2(acc1[j], zb.x, w.x);
                fma2(acc1[j], zb.y, w.y);
            }
        }
        __syncthreads();
    }

    // psum overlay on zbuf: psum[ch][row(128)][12]
#pragma unroll
    for (int j = 0; j < 6; j++) {
        float2 u0 = unpack2(acc0[j]);
        float2 u1 = unpack2(acc1[j]);
        psum[ch * 1536 + mg * 12 + hg * 6 + j] = u0.x + u0.y;
        psum[ch * 1536 + (mg + 64) * 12 + hg * 6 + j] = u1.x + u1.y;
    }
    __syncthreads();

    const float s3 = 0.5773502691896258f;
    for (int out = tid; out < 128 * HN; out += 256) {
        int h = out >> 7, m = out & 127;       // m fastest -> coalesced
        float dot = psum[m * 12 + h] + psum[1536 + m * 12 + h];
        g_b[((size_t)h * NRES + n) * NRES + m0 + m] = s3 * (dot + bsh[h]);
    }
}

// qkpt: E = s1*qk - |wpt|*ptdist + mask -> g_a
__device__ void qkpt_body(float* sh, const float* __restrict__ mask,
                          const float* __restrict__ head_weights,
                          int h, int n0, int m0) {
    float (*Qs)[68] = (float(*)[68])sh;
    float (*Ks)[68] = (float(*)[68])(sh + 28 * 68);
    const int tid = threadIdx.x;
    const float s1 = 0.14433756729740643f;
    const float hw = log1pf(expf(head_weights[h]));
    const float wpt_abs = 0.5f * hw * 0.13608276348795434f;
    const float sp = sqrtf(wpt_abs);

    for (int idx = tid; idx < 64 * 32; idx += 256) {
        int c = idx & 31, r = idx >> 5;
        if (c < 16) {
            Qs[c][r] = s1 * g_q[(n0 + r) * 192 + h * 16 + c];
            Ks[c][r] = g_kv[(size_t)(m0 + r) * 384 + h * 32 + c];
        } else if (c < 28) {
            Qs[c][r] = sp * g_qpts[(n0 + r) * 144 + h * 12 + (c - 16)];
            Ks[c][r] = sp * g_kpts[(m0 + r) * 144 + h * 12 + (c - 16)];
        }
    }
    __syncthreads();
    const int ty = tid >> 4, tx = tid & 15;
    float acc[4][4];
#pragma unroll
    for (int i = 0; i < 4; i++)
#pragma unroll
        for (int j = 0; j < 4; j++) acc[i][j] = 0.f;

#pragma unroll
    for (int c = 0; c < 16; c++) {
        float ra[4], rb[4];
#pragma unroll
        for (int i = 0; i < 4; i++) ra[i] = Qs[c][ty * 4 + i];
#pragma unroll
        for (int j = 0; j < 4; j++) rb[j] = Ks[c][tx * 4 + j];
#pragma unroll
        for (int i = 0; i < 4; i++)
#pragma unroll
            for (int j = 0; j < 4; j++) acc[i][j] += ra[i] * rb[j];
    }
#pragma unroll
    for (int c = 16; c < 28; c++) {
        float ra[4], rb[4];
#pragma unroll
        for (int i = 0; i < 4; i++) ra[i] = Qs[c][ty * 4 + i];
#pragma unroll
        for (int j = 0; j < 4; j++) rb[j] = Ks[c][tx * 4 + j];
#pragma unroll
        for (int i = 0; i < 4; i++)
#pragma unroll
            for (int j = 0; j < 4; j++) {
                float d = ra[i] - rb[j];
                acc[i][j] = fmaf(-d, d, acc[i][j]);
            }
    }
#pragma unroll
    for (int i = 0; i < 4; i++) {
        int n = n0 + ty * 4 + i;
        float mn = mask[n];
#pragma unroll
        for (int j = 0; j < 4; j++) {
            int m = m0 + tx * 4 + j;
            g_a[((size_t)h * NRES + n) * NRES + m] =
                acc[i][j] + (mn * mask[m] - 1.f) * 100000.f;
        }
    }
}

// phase1: interleave 8 bmat : 3 qkpt per group of 11 blocks (4608 + 1728)
__global__ __launch_bounds__(256, 4) void k_phase1(
        const float* __restrict__ z, const float* __restrict__ w_b,
        const float* __restrict__ b_b, const float* __restrict__ mask,
        const float* __restrict__ head_weights) {
    extern __shared__ float sh[];
    const int q = blockIdx.x / 11, r = blockIdx.x % 11;
    if (r < 8) {
        int b = q * 8 + r;
        bmat_body(sh, z, w_b, b_b, (b % 6) * 128, b / 6);
    } else {
        int t = q * 3 + (r - 8);              // 0..1727
        int h = t % 12; t /= 12;
        qkpt_body(sh, mask, head_weights, h, (t % 12) * 64, (t / 12) * 64);
    }
}

// ---------------- softmax over m: a = softmax(E + B), float4 + shuffle -------
__global__ void k_softmax() {
    __shared__ float red[8];
    const size_t row = blockIdx.x;
    float4* a4 = (float4*)(g_a + row * NRES);
    const float4* b4 = (const float4*)(g_b + row * NRES);
    const int t = threadIdx.x;             // 192 threads, 1 float4 each
    const int lane = t & 31, wid = t >> 5;
    float4 v = a4[t];
    float4 bb = b4[t];
    v.x += bb.x; v.y += bb.y; v.z += bb.z; v.w += bb.w;
    float mx = fmaxf(fmaxf(v.x, v.y), fmaxf(v.z, v.w));
#pragma unroll
    for (int o = 16; o > 0; o >>= 1) mx = fmaxf(mx, __shfl_xor_sync(0xffffffffu, mx, o));
    if (lane == 0) red[wid] = mx;
    __syncthreads();
    mx = fmaxf(fmaxf(red[0], red[1]),
               fmaxf(fmaxf(red[2], red[3]), fmaxf(red[4], red[5])));
    __syncthreads();                        // red reads done before reuse
    v.x = __expf(v.x - mx); v.y = __expf(v.y - mx);
    v.z = __expf(v.z - mx); v.w = __expf(v.w - mx);
    float sum = v.x + v.y + v.z + v.w;
#pragma unroll
    for (int o = 16; o > 0; o >>= 1) sum += __shfl_xor_sync(0xffffffffu, sum, o);
    if (lane == 0) red[wid] = sum;
    __syncthreads();
    float inv = 1.f / (red[0] + red[1] + red[2] + red[3] + red[4] + red[5]);
    v.x *= inv; v.y *= inv; v.z *= inv; v.w *= inv;
    a4[t] = v;
}

// ---------------- phase2 bodies ----------------------------------------------
// opair: triple-buffered 16m chunks; ash [m][16] (h at (h/6)*8 + h%6);
// lane = 4c x 6 heads, f32x2 over c-pairs; psum overlays zbuf.
#define O6_CH   16
#define O6_NCH  24
#define O6_BUF  (O6_CH * CZ)                   // 2048 words
#define O6_ASZ  (384 * 16)                     // 6144 padded transposed
#define P2_SMEM ((3 * O6_BUF + O6_ASZ) * 4)    // 48 KB
__device__ void opair_body(float* sh, const float* __restrict__ z, int n, int half) {
    float* zbuf = sh;                          // 3 x 2048
    float* ash  = sh + 3 * O6_BUF;             // [384][16]
    float* psum = sh;                          // overlay on zbuf: [4][12][128] = 6144
    const int tid  = threadIdx.x;
    const int mbase = half * 384;
    const float* zsrc = z + ((size_t)n * NRES + mbase) * CZ;

    // prefetch chunks 0,1
#pragma unroll
    for (int k = 0; k < 2; k++) {
        unsigned dstb = smem_u32(zbuf + k * O6_BUF);
        const float* src = zsrc + (size_t)k * O6_CH * CZ;
#pragma unroll
        for (int j = 0; j < 2; j++) {
            int i = tid + j * 256;             // 512 float4
            cp_async16(dstb + i * 16, src + i * 4);
        }
        CP_COMMIT();
    }

    // transposed a staging: ash[m][ (h/6)*8 + h%6 ]
    for (int idx = tid; idx < HN * 384; idx += 256) {
        int h = idx / 384, m = idx - h * 384;
        int col = (h / 6) * 8 + (h % 6);
        ash[m * 16 + col] = g_a[((size_t)h * NRES + n) * NRES + mbase + m];
    }

    const int mw = tid >> 6;         // 0..3  m-group (4 m each per chunk)
    const int hg = (tid >> 5) & 1;   // head group (6 heads)
    const int cg = tid & 31;         // 4 c's per lane
    u64 acc2[6][2];                  // [head][c-pair]
#pragma unroll
    for (int j = 0; j < 6; j++) { acc2[j][0] = 0ull; acc2[j][1] = 0ull; }

    for (int k = 0; k < O6_NCH; k++) {
        if (k + 2 < O6_NCH) {
            unsigned dstb = smem_u32(zbuf + ((k + 2) % 3) * O6_BUF);
            const float* src = zsrc + (size_t)(k + 2) * O6_CH * CZ;
#pragma unroll
            for (int j = 0; j < 2; j++) {
                int i = tid + j * 256;
                cp_async16(dstb + i * 16, src + i * 4);
            }
            CP_COMMIT();
            CP_WAIT(2);
        } else if (k + 1 < O6_NCH) {
            CP_WAIT(1);
        } else {
            CP_WAIT(0);
        }
        __syncthreads();

        const float* zb = zbuf + (k % 3) * O6_BUF;
        const int mg0 = k * O6_CH + mw * 4;
#pragma unroll
        for (int mm = 0; mm < 4; mm++) {
            int ml = mw * 4 + mm;
            ulonglong2 zv = *(const ulonglong2*)&zb[ml * CZ + cg * 4];
            const float* ar = &ash[(mg0 + mm) * 16 + hg * 8];
            float4 a0 = *(const float4*)&ar[0];
            float2 a1 = *(const float2*)&ar[4];
            u64 ad[6] = {dup2(a0.x), dup2(a0.y), dup2(a0.z),
                         dup2(a0.w), dup2(a1.x), dup2(a1.y)};
#pragma unroll
            for (int j = 0; j < 6; j++) {
                fma2(acc2[j][0], ad[j], zv.x);
                fma2(acc2[j][1], ad[j], zv.y);
            }
        }
        __syncthreads();
    }

    // psum overlay: psum[mw][12][128]
#pragma unroll
    for (int j = 0; j < 6; j++) {
        float2 u0 = unpack2(acc2[j][0]);
        float2 u1 = unpack2(acc2[j][1]);
        *(float4*)&psum[mw * 1536 + (hg * 6 + j) * CZ + cg * 4] =
            make_float4(u0.x, u0.y, u1.x, u1.y);
    }
    __syncthreads();
    for (int out = tid; out < HN * CZ; out += 256) {
        const float* pb = psum + out;
        float s = pb[0] + pb[1536] + pb[3072] + pb[4608];
        g_opp[((size_t)half * NRES + n) * (HN * CZ) + out] = s;
    }
}

// av: o = a@v, o_pt = a@v_pts (global frame)
__device__ void av_body(float* sh, int h, int n0) {
    float* ash = sh;                 // 64*65
    float* vsh = sh + 64 * 65;       // 64*48
    const int tid = threadIdx.x;
    const int nq = tid & 15, cg = tid >> 4;
    float acc[4][3];
#pragma unroll
    for (int i = 0; i < 4; i++)
#pragma unroll
        for (int j = 0; j < 3; j++) acc[i][j] = 0.f;

    for (int mt = 0; mt < 12; mt++) {
        const int m0 = mt * 64;
        __syncthreads();
        for (int idx = tid; idx < 4096; idx += 256) {
            int nn = idx >> 6, mm = idx & 63;
            ash[nn * 65 + mm] = g_a[((size_t)h * NRES + n0 + nn) * NRES + m0 + mm];
        }
        for (int idx = tid; idx < 64 * 48; idx += 256) {
            int mm = idx / 48, c = idx % 48;
            float v = 0.f;
            if (c < 16)      v = g_kv[(size_t)(m0 + mm) * 384 + h * 32 + 16 + c];
            else if (c < 40) v = g_vpts[(m0 + mm) * 288 + h * 24 + (c - 16)];
            vsh[mm * 48 + c] = v;
        }
        __syncthreads();
#pragma unroll 4
        for (int mm = 0; mm < 64; mm++) {
            float ra[4], rv[3];
#pragma unroll
            for (int i = 0; i < 4; i++) ra[i] = ash[(nq + 16 * i) * 65 + mm];
#pragma unroll
            for (int j = 0; j < 3; j++) rv[j] = vsh[mm * 48 + cg + 16 * j];
#pragma unroll
            for (int i = 0; i < 4; i++)
#pragma unroll
                for (int j = 0; j < 3; j++) acc[i][j] += ra[i] * rv[j];
        }
    }
#pragma unroll
    for (int i = 0; i < 4; i++) {
        int n = n0 + nq + 16 * i;
#pragma unroll
        for (int j = 0; j < 3; j++) {
            int c = cg + 16 * j;
            if (c < 40) g_obuf[((size_t)n * 12 + h) * 40 + c] = acc[i][j];
        }
    }
}

// phase2: interleave 32 opair : 3 av per group of 35 blocks (1536 + 144)
__global__ __launch_bounds__(256, 4) void k_phase2(const float* __restrict__ z) {
    extern __shared__ float sh[];
    const int q = blockIdx.x / 35, r = blockIdx.x % 35;
    if (r < 32) {
        int b = q * 32 + r;
        opair_body(sh, z, b >> 1, b & 1);
    } else {
        int t = q * 3 + (r - 32);             // 0..143
        av_body(sh, t % 12, (t / 12) * 64);
    }
}

// ---------------- finalize: o_pt local frame, norms, concat, opp sum --------
__global__ void k_finish(const float* __restrict__ rot, const float* __restrict__ trans) {
    const int n = blockIdx.x;
    const int t = threadIdx.x;   // 192
    if (t < 96) {
        int h = t >> 3, p = t & 7;
        const float* ob = &g_obuf[((size_t)n * 12 + h) * 40 + 16 + p * 3];
        float gx = ob[0] - trans[n * 3 + 0];
        float gy = ob[1] - trans[n * 3 + 1];
        float gz = ob[2] - trans[n * 3 + 2];
        const float* r = rot + n * 9;
        float lx = r[0] * gx + r[3] * gy + r[6] * gz;
        float ly = r[1] * gx + r[4] * gy + r[7] * gz;
        float lz = r[2] * gx + r[5] * gy + r[8] * gz;
        size_t base = (size_t)n * 2112;
        g_ocat[base + 192 + t] = lx;
        g_ocat[base + 288 + t] = ly;
        g_ocat[base + 384 + t] = lz;
        g_ocat[base + 480 + t] = sqrtf(lx * lx + ly * ly + lz * lz + 1e-8f);
    }
    g_ocat[(size_t)n * 2112 + t] = g_obuf[((size_t)n * 12 + (t >> 4)) * 40 + (t & 15)];
    for (int i = t; i < HN * CZ; i += 192) {
        g_ocat[(size_t)n * 2112 + 576 + i] =
            g_opp[(size_t)n * (HN * CZ) + i] +
            g_opp[((size_t)NRES + n) * (HN * CZ) + i];
    }
}

// ---------------- launcher ---------------------------------------------------
extern "C" void kernel_launch(void* const* d_in, const int* in_sizes, int n_in,
                              void* d_out, int out_size) {
    const float* s      = (const float*)d_in[0];
    const float* z      = (const float*)d_in[1];
    const float* rot    = (const float*)d_in[2];
    const float* trans  = (const float*)d_in[3];
    const float* mask   = (const float*)d_in[4];
    const float* w_q    = (const float*)d_in[5];
    const float* b_q    = (const float*)d_in[6];
    const float* w_kv   = (const float*)d_in[7];
    const float* b_kv   = (const float*)d_in[8];
    const float* w_qp   = (const float*)d_in[9];
    const float* b_qp   = (const float*)d_in[10];
    const float* w_kvp  = (const float*)d_in[11];
    const float* b_kvp  = (const float*)d_in[12];
    const float* w_b    = (const float*)d_in[13];
    const float* b_b    = (const float*)d_in[14];
    const float* hwts   = (const float*)d_in[15];
    const float* w_out  = (const float*)d_in[16];
    const float* b_out  = (const float*)d_in[17];
    float* out = (float*)d_out;

    float *pq, *pkv, *pqp, *pkvp, *pocat, *ppart;
    cudaGetSymbolAddress((void**)&pq,    g_q);
    cudaGetSymbolAddress((void**)&pkv,   g_kv);
    cudaGetSymbolAddress((void**)&pqp,   g_qp);
    cudaGetSymbolAddress((void**)&pkvp,  g_kvp);
    cudaGetSymbolAddress((void**)&pocat, g_ocat);
    cudaGetSymbolAddress((void**)&ppart, g_part);

    cudaFuncSetAttribute(k_phase1, cudaFuncAttributeMaxDynamicSharedMemorySize, B4_SMEM);
    cudaFuncSetAttribute(k_phase2, cudaFuncAttributeMaxDynamicSharedMemorySize, P2_SMEM);

    // projections (one launch)
    gemm_proj<<<dim3(19, 12), 256>>>(s, w_q, b_q, pq, w_kv, b_kv, pkv,
                                     w_qp, b_qp, pqp, w_kvp, b_kvp, pkvp);
    // point transform
    k_points<<<NRES, 192>>>(rot, trans);
    // phase1: bmat (z pass 1) + qkpt interleaved
    k_phase1<<<6336, 256, B4_SMEM>>>(z, w_b, b_b, mask, hwts);
    // softmax(E + B) -> g_a
    k_softmax<<<HN * NRES, 192>>>();
    // phase2: opair (z pass 2) + av interleaved
    k_phase2<<<1680, 256, P2_SMEM>>>(z);
    k_finish<<<NRES, 192>>>(rot, trans);
    // output projection: split-K x3 + combine
    gemm_out<<<dim3(6, 12, 3), 256>>>(pocat, w_out, ppart);
    k_outadd<<<NRES, CS>>>(b_out, out);
}